// round 1
// baseline (speedup 1.0000x reference)
#include <cuda_runtime.h>
#include <math.h>

#define BATCH 8
#define LC    2048
#define LQ    1024
#define DIM   768
#define ODIM  1536

__device__ __constant__ float kSCALE = 0.03608439182435161f; // 1/sqrt(768)

// Scratch (allocation-free rule: __device__ globals)
__device__ float g_query[BATCH * LQ * DIM];            // 25 MB
__device__ float g_scores[(size_t)BATCH * LC * LQ];    // 67 MB

// ---------------------------------------------------------------------------
// 128x128 tile SGEMM core. 256 threads, 8x8 per-thread microtile, BK=8.
// TRANS_B = true : B is [n, k] row-major (k contiguous)  -> C = A * B^T
// TRANS_B = false: B is [k, n] row-major (n contiguous)  -> C = A * B
// A is always [m, k] row-major. Caller pre-offsets A to the block row and
// B to the block col (row n0 for TRANS_B, column offset for !TRANS_B).
// All dims assumed divisible (they are for this problem).
// ---------------------------------------------------------------------------
template <bool TRANS_B>
__device__ __forceinline__ void gemm_tile(const float* __restrict__ A,
                                          const float* __restrict__ Bm,
                                          int K, int lda, int ldb,
                                          float acc[8][8]) {
    __shared__ float As[8][128];
    __shared__ float Bs[8][128];

    const int tid = threadIdx.x;
    const int tx  = tid & 15;   // 0..15 col group
    const int ty  = tid >> 4;   // 0..15 row group

    // A loader: 128 rows x 8 k, one float4 per thread
    const int a_row = tid >> 1;        // 0..127
    const int a_col = (tid & 1) * 4;   // 0 or 4
    // B loader (!TRANS_B): 8 k x 128 n, one float4 per thread
    const int bn_row = tid >> 5;       // 0..7
    const int bn_col = (tid & 31) * 4; // 0..124

    for (int k0 = 0; k0 < K; k0 += 8) {
        float4 av = *reinterpret_cast<const float4*>(A + (size_t)a_row * lda + k0 + a_col);
        As[a_col + 0][a_row] = av.x;
        As[a_col + 1][a_row] = av.y;
        As[a_col + 2][a_row] = av.z;
        As[a_col + 3][a_row] = av.w;
        if (TRANS_B) {
            float4 bv = *reinterpret_cast<const float4*>(Bm + (size_t)a_row * ldb + k0 + a_col);
            Bs[a_col + 0][a_row] = bv.x;
            Bs[a_col + 1][a_row] = bv.y;
            Bs[a_col + 2][a_row] = bv.z;
            Bs[a_col + 3][a_row] = bv.w;
        } else {
            float4 bv = *reinterpret_cast<const float4*>(Bm + (size_t)(k0 + bn_row) * ldb + bn_col);
            *reinterpret_cast<float4*>(&Bs[bn_row][bn_col]) = bv;
        }
        __syncthreads();

        #pragma unroll
        for (int kk = 0; kk < 8; kk++) {
            float ra[8], rb[8];
            *reinterpret_cast<float4*>(&ra[0]) = *reinterpret_cast<const float4*>(&As[kk][ty * 8]);
            *reinterpret_cast<float4*>(&ra[4]) = *reinterpret_cast<const float4*>(&As[kk][ty * 8 + 4]);
            *reinterpret_cast<float4*>(&rb[0]) = *reinterpret_cast<const float4*>(&Bs[kk][tx * 8]);
            *reinterpret_cast<float4*>(&rb[4]) = *reinterpret_cast<const float4*>(&Bs[kk][tx * 8 + 4]);
            #pragma unroll
            for (int i = 0; i < 8; i++)
                #pragma unroll
                for (int j = 0; j < 8; j++)
                    acc[i][j] = fmaf(ra[i], rb[j], acc[i][j]);
        }
        __syncthreads();
    }
}

// ---------------------------------------------------------------------------
// K1: query[m, e] = sum_d qh[m, d] * W[e, d] + b[e];  m = b*LQ + q  (M=8192)
// grid: (DIM/128=6, 8192/128=64)
// ---------------------------------------------------------------------------
__global__ __launch_bounds__(256) void k_query(const float* __restrict__ qh,
                                               const float* __restrict__ W,
                                               const float* __restrict__ bias) {
    float acc[8][8] = {};
    const float* A  = qh + (size_t)blockIdx.y * 128 * DIM;
    const float* Bm = W  + (size_t)blockIdx.x * 128 * DIM;
    gemm_tile<true>(A, Bm, DIM, DIM, DIM, acc);

    const int tx = threadIdx.x & 15, ty = threadIdx.x >> 4;
    const int row0 = blockIdx.y * 128 + ty * 8;
    const int col0 = blockIdx.x * 128 + tx * 8;
    #pragma unroll
    for (int i = 0; i < 8; i++) {
        float* out = g_query + (size_t)(row0 + i) * DIM + col0;
        #pragma unroll
        for (int j = 0; j < 8; j++) out[j] = acc[i][j] + bias[col0 + j];
    }
}

// ---------------------------------------------------------------------------
// K2: scores[b][c, q] = SCALE * sum_d ch[b,c,d]*query[b,q,d]; mask -> -1e30
// grid: (LQ/128=8, LC/128=16, BATCH)
// ---------------------------------------------------------------------------
__global__ __launch_bounds__(256) void k_scores(const float* __restrict__ ch,
                                                const int* __restrict__ qmask) {
    const int z = blockIdx.z;
    float acc[8][8] = {};
    const float* A  = ch + (size_t)z * LC * DIM + (size_t)blockIdx.y * 128 * DIM;
    const float* Bm = g_query + (size_t)z * LQ * DIM + (size_t)blockIdx.x * 128 * DIM;
    gemm_tile<true>(A, Bm, DIM, DIM, DIM, acc);

    const int tx = threadIdx.x & 15, ty = threadIdx.x >> 4;
    const int row0 = blockIdx.y * 128 + ty * 8;
    const int col0 = blockIdx.x * 128 + tx * 8;
    int mk[8];
    #pragma unroll
    for (int j = 0; j < 8; j++) mk[j] = qmask[z * LQ + col0 + j];
    float* sbase = g_scores + (size_t)z * LC * LQ;
    #pragma unroll
    for (int i = 0; i < 8; i++) {
        float* out = sbase + (size_t)(row0 + i) * LQ + col0;
        #pragma unroll
        for (int j = 0; j < 8; j++) {
            float v = acc[i][j] * kSCALE;
            out[j] = mk[j] ? v : -1e30f;
        }
    }
}

// ---------------------------------------------------------------------------
// K3: softmax over each row of g_scores (row length LQ=1024), in place.
// grid: BATCH*LC blocks, 256 threads, float4 per thread.
// ---------------------------------------------------------------------------
__global__ __launch_bounds__(256) void k_softmax() {
    float* p = g_scores + (size_t)blockIdx.x * LQ;
    const int t = threadIdx.x;
    float4 v = reinterpret_cast<float4*>(p)[t];

    __shared__ float red[8];
    // max
    float m = fmaxf(fmaxf(v.x, v.y), fmaxf(v.z, v.w));
    #pragma unroll
    for (int o = 16; o; o >>= 1) m = fmaxf(m, __shfl_xor_sync(0xffffffffu, m, o));
    if ((t & 31) == 0) red[t >> 5] = m;
    __syncthreads();
    m = red[0];
    #pragma unroll
    for (int w = 1; w < 8; w++) m = fmaxf(m, red[w]);
    __syncthreads();

    // exp + sum
    v.x = expf(v.x - m); v.y = expf(v.y - m);
    v.z = expf(v.z - m); v.w = expf(v.w - m);
    float s = v.x + v.y + v.z + v.w;
    #pragma unroll
    for (int o = 16; o; o >>= 1) s += __shfl_xor_sync(0xffffffffu, s, o);
    if ((t & 31) == 0) red[t >> 5] = s;
    __syncthreads();
    s = red[0];
    #pragma unroll
    for (int w = 1; w < 8; w++) s += red[w];

    float inv = 1.0f / s;
    v.x *= inv; v.y *= inv; v.z *= inv; v.w *= inv;
    reinterpret_cast<float4*>(p)[t] = v;
}

// ---------------------------------------------------------------------------
// K4: attn[b][c, d] = sum_q P[b][c, q] * qh[b][q, d]  (NN GEMM, K=LQ)
// writes into out columns [768, 1536)
// grid: (DIM/128=6, LC/128=16, BATCH)
// ---------------------------------------------------------------------------
__global__ __launch_bounds__(256) void k_out(const float* __restrict__ qh,
                                             float* __restrict__ out) {
    const int z = blockIdx.z;
    float acc[8][8] = {};
    const float* A  = g_scores + (size_t)z * LC * LQ + (size_t)blockIdx.y * 128 * LQ;
    const float* Bm = qh + (size_t)z * LQ * DIM + (size_t)blockIdx.x * 128;
    gemm_tile<false>(A, Bm, LQ, LQ, DIM, acc);

    const int tx = threadIdx.x & 15, ty = threadIdx.x >> 4;
    const int row0 = blockIdx.y * 128 + ty * 8;
    const int col0 = blockIdx.x * 128 + tx * 8;
    float* obase = out + (size_t)z * LC * ODIM + DIM;
    #pragma unroll
    for (int i = 0; i < 8; i++) {
        float* o = obase + (size_t)(row0 + i) * ODIM + col0;
        #pragma unroll
        for (int j = 0; j < 4; j++) {
            // pairwise float2 stores
            *reinterpret_cast<float2*>(o + 2 * j) = make_float2(acc[i][2 * j], acc[i][2 * j + 1]);
        }
        #pragma unroll
        for (int j = 4; j < 8; j++) o[j] = acc[i][j];
    }
}

// ---------------------------------------------------------------------------
// K5: out[b][c][0:768] = context_hiddens
// ---------------------------------------------------------------------------
__global__ __launch_bounds__(256) void k_copy(const float* __restrict__ ch,
                                              float* __restrict__ out) {
    const size_t total4 = (size_t)BATCH * LC * (DIM / 4);
    for (size_t idx = (size_t)blockIdx.x * blockDim.x + threadIdx.x; idx < total4;
         idx += (size_t)gridDim.x * blockDim.x) {
        size_t row = idx / (DIM / 4);
        size_t d4  = idx % (DIM / 4);
        reinterpret_cast<float4*>(out)[row * (ODIM / 4) + d4] =
            reinterpret_cast<const float4*>(ch)[idx];
    }
}

extern "C" void kernel_launch(void* const* d_in, const int* in_sizes, int n_in,
                              void* d_out, int out_size) {
    const float* ch    = (const float*)d_in[0];
    // d_in[1] = context_mask (unused by forward)
    const float* qh    = (const float*)d_in[2];
    const int*   qmask = (const int*)d_in[3];
    const float* W     = (const float*)d_in[4];
    const float* bias  = (const float*)d_in[5];
    float*       out   = (float*)d_out;

    k_query<<<dim3(DIM / 128, (BATCH * LQ) / 128), 256>>>(qh, W, bias);
    k_scores<<<dim3(LQ / 128, LC / 128, BATCH), 256>>>(ch, qmask);
    k_softmax<<<BATCH * LC, 256>>>();
    k_out<<<dim3(DIM / 128, LC / 128, BATCH), 256>>>(qh, out);
    k_copy<<<1184, 256>>>(ch, out);
}

// round 3
// speedup vs baseline: 3.0571x; 3.0571x over previous
#include <cuda_runtime.h>
#include <cuda_bf16.h>
#include <cstdint>

#define BATCH 8
#define LC    2048
#define LQ    1024
#define DIM   768
#define ODIM  1536

#define NEG_INF (-1e30f)
#define SCALE_F 0.03608439182435161f  // 1/sqrt(768)

// ---------------------------------------------------------------------------
// Scratch (__device__ globals; allocation-free rule)
// ---------------------------------------------------------------------------
__device__ __align__(16) __nv_bfloat16 g_chh[(size_t)BATCH * LC * DIM];
__device__ __align__(16) __nv_bfloat16 g_chl[(size_t)BATCH * LC * DIM];
__device__ __align__(16) __nv_bfloat16 g_qhh[(size_t)BATCH * LQ * DIM];
__device__ __align__(16) __nv_bfloat16 g_qhl[(size_t)BATCH * LQ * DIM];
__device__ __align__(16) __nv_bfloat16 g_qth[(size_t)BATCH * DIM * LQ];  // qh^T [b, d, q]
__device__ __align__(16) __nv_bfloat16 g_qtl[(size_t)BATCH * DIM * LQ];
__device__ __align__(16) __nv_bfloat16 g_wh[DIM * DIM];
__device__ __align__(16) __nv_bfloat16 g_wl[DIM * DIM];
__device__ __align__(16) __nv_bfloat16 g_qryh[(size_t)BATCH * LQ * DIM];
__device__ __align__(16) __nv_bfloat16 g_qryl[(size_t)BATCH * LQ * DIM];
__device__ __align__(16) float         g_scores[(size_t)BATCH * LC * LQ];
__device__ __align__(16) __nv_bfloat16 g_ph[(size_t)BATCH * LC * LQ];
__device__ __align__(16) __nv_bfloat16 g_pl[(size_t)BATCH * LC * LQ];

// ---------------------------------------------------------------------------
// helpers
// ---------------------------------------------------------------------------
static __device__ __forceinline__ uint32_t smem_u32(const void* p) {
    uint32_t r;
    asm("{ .reg .u64 t; cvta.to.shared.u64 t, %1; cvt.u32.u64 %0, t; }"
        : "=r"(r) : "l"(p));
    return r;
}

static __device__ __forceinline__ void cp16(uint32_t dst, const void* src) {
    asm volatile("cp.async.cg.shared.global [%0], [%1], 16;" :: "r"(dst), "l"(src));
}

static __device__ __forceinline__ void split2(float x, __nv_bfloat16& h, __nv_bfloat16& l) {
    h = __float2bfloat16_rn(x);
    l = __float2bfloat16_rn(x - __bfloat162float(h));
}
static __device__ __forceinline__ uint32_t packbf(__nv_bfloat16 a, __nv_bfloat16 b) {
    __nv_bfloat162 t = __halves2bfloat162(a, b);
    return *reinterpret_cast<uint32_t*>(&t);
}

#define LDSM_X4(r0, r1, r2, r3, addr) \
    asm volatile("ldmatrix.sync.aligned.m8n8.x4.shared.b16 {%0,%1,%2,%3}, [%4];" \
                 : "=r"(r0), "=r"(r1), "=r"(r2), "=r"(r3) : "r"(addr))

#define MMA16816(d, a, b) \
    asm volatile("mma.sync.aligned.m16n8k16.row.col.f32.bf16.bf16.f32 " \
                 "{%0,%1,%2,%3}, {%4,%5,%6,%7}, {%8,%9}, {%0,%1,%2,%3};" \
                 : "+f"((d)[0]), "+f"((d)[1]), "+f"((d)[2]), "+f"((d)[3]) \
                 : "r"((a)[0]), "r"((a)[1]), "r"((a)[2]), "r"((a)[3]), \
                   "r"((b)[0]), "r"((b)[1]))

// ---------------------------------------------------------------------------
// SMEM: 2 buffers x 4 tiles (Ah, Al, Bh, Bl) x 16384B.
// Tile: 128 rows x 64 bf16 (128B rows), XOR-swizzled at 16B granularity.
// ---------------------------------------------------------------------------
#define TILE_B   16384
#define BUF_B    (4 * TILE_B)
#define SMEM_DYN (2 * BUF_B)

static __device__ __forceinline__ uint32_t swz(uint32_t row, uint32_t kbyte) {
    return (row * 128 + kbyte) ^ ((row & 7) << 4);
}

static __device__ __forceinline__ void load_chunk(
    uint32_t bufbase,
    const __nv_bfloat16* __restrict__ Ah, const __nv_bfloat16* __restrict__ Al, int ldA,
    const __nv_bfloat16* __restrict__ Bh, const __nv_bfloat16* __restrict__ Bl, int ldB,
    int k0, int tid) {
    const __nv_bfloat16* srcs[4] = {Ah, Al, Bh, Bl};
    #pragma unroll
    for (int t = 0; t < 4; t++) {
        const __nv_bfloat16* s = srcs[t];
        int ld = (t < 2) ? ldA : ldB;
        uint32_t tb = bufbase + t * TILE_B;
        #pragma unroll
        for (int i = 0; i < 4; i++) {
            int idx = tid + i * 256;           // 0..1023
            int row = idx >> 3, seg = idx & 7; // 128 rows x 8 x 16B
            cp16(tb + swz(row, seg * 16), (const void*)(s + (size_t)row * ld + k0 + seg * 8));
        }
    }
    asm volatile("cp.async.commit_group;" ::: "memory");
}

// One 64-k chunk of compute for this warp (tile 64x32), 3-pass bf16 split.
static __device__ __forceinline__ void compute_chunk(uint32_t tb, int wm, int wn, int lane,
                                                     float acc[4][4][4]) {
    const uint32_t tbAh = tb, tbAl = tb + TILE_B, tbBh = tb + 2 * TILE_B, tbBl = tb + 3 * TILE_B;
    #pragma unroll
    for (int ks = 0; ks < 4; ks++) {
        const uint32_t k0 = ks * 16;
        // A fragments: 4 m-tiles (16 rows each), hi + lo
        uint32_t ah[4][4], al[4][4];
        {
            const uint32_t arow = wm * 64 + (lane & 15);
            const uint32_t akc = k0 + ((lane >> 4) << 3);
            #pragma unroll
            for (int tm = 0; tm < 4; tm++) {
                uint32_t off = swz(arow + tm * 16, akc * 2);
                LDSM_X4(ah[tm][0], ah[tm][1], ah[tm][2], ah[tm][3], tbAh + off);
                LDSM_X4(al[tm][0], al[tm][1], al[tm][2], al[tm][3], tbAl + off);
            }
        }
        // B fragments: 4 n8-tiles (two x4 loads cover 16 n-rows each), hi + lo
        uint32_t bh[4][2], bl[4][2];
        {
            const uint32_t brow = wn * 32 + (lane & 7) + ((lane >> 4) << 3);
            const uint32_t bkc = k0 + (((lane >> 3) & 1) << 3);
            #pragma unroll
            for (int tp = 0; tp < 2; tp++) {
                uint32_t off = swz(brow + tp * 16, bkc * 2);
                uint32_t t0, t1, t2, t3;
                LDSM_X4(t0, t1, t2, t3, tbBh + off);
                bh[tp * 2][0] = t0; bh[tp * 2][1] = t1;
                bh[tp * 2 + 1][0] = t2; bh[tp * 2 + 1][1] = t3;
                LDSM_X4(t0, t1, t2, t3, tbBl + off);
                bl[tp * 2][0] = t0; bl[tp * 2][1] = t1;
                bl[tp * 2 + 1][0] = t2; bl[tp * 2 + 1][1] = t3;
            }
        }
        #pragma unroll
        for (int tm = 0; tm < 4; tm++)
            #pragma unroll
            for (int tn = 0; tn < 4; tn++) {
                MMA16816(acc[tm][tn], ah[tm], bh[tn]);
                MMA16816(acc[tm][tn], ah[tm], bl[tn]);
                MMA16816(acc[tm][tn], al[tm], bh[tn]);
            }
    }
}

static __device__ __forceinline__ void mainloop(
    const __nv_bfloat16* __restrict__ Ah, const __nv_bfloat16* __restrict__ Al, int ldA,
    const __nv_bfloat16* __restrict__ Bh, const __nv_bfloat16* __restrict__ Bl, int ldB,
    int nk, float acc[4][4][4]) {
    extern __shared__ char smem[];
    const uint32_t sb = smem_u32(smem);
    const int tid = threadIdx.x, lane = tid & 31, wid = tid >> 5;
    const int wm = wid & 1, wn = wid >> 1;

    load_chunk(sb, Ah, Al, ldA, Bh, Bl, ldB, 0, tid);
    for (int k = 0; k < nk; k++) {
        if (k + 1 < nk) {
            load_chunk(sb + ((k + 1) & 1) * BUF_B, Ah, Al, ldA, Bh, Bl, ldB, (k + 1) * 64, tid);
            asm volatile("cp.async.wait_group 1;" ::: "memory");
        } else {
            asm volatile("cp.async.wait_group 0;" ::: "memory");
        }
        __syncthreads();
        compute_chunk(sb + (k & 1) * BUF_B, wm, wn, lane, acc);
        __syncthreads();
    }
}

// ---------------------------------------------------------------------------
// GEMM 1: query[m, e] = qh[m, :] . W[e, :] + b[e]; bf16 hi/lo out. grid (6, 64)
// ---------------------------------------------------------------------------
__global__ __launch_bounds__(256, 1) void k_gemm_query(const float* __restrict__ bias) {
    float acc[4][4][4] = {};
    const size_t aoff = (size_t)blockIdx.y * 128 * DIM;
    const size_t boff = (size_t)blockIdx.x * 128 * DIM;
    mainloop(g_qhh + aoff, g_qhl + aoff, DIM, g_wh + boff, g_wl + boff, DIM, DIM / 64, acc);

    const int lane = threadIdx.x & 31, wid = threadIdx.x >> 5;
    const int wm = wid & 1, wn = wid >> 1;
    const int gr = lane >> 2, gc = (lane & 3) * 2;
    const int row0 = blockIdx.y * 128 + wm * 64, col0 = blockIdx.x * 128 + wn * 32;
    #pragma unroll
    for (int tn = 0; tn < 4; tn++) {
        const int c = col0 + tn * 8 + gc;
        const float2 bb = *reinterpret_cast<const float2*>(bias + c);
        #pragma unroll
        for (int tm = 0; tm < 4; tm++)
            #pragma unroll
            for (int hf = 0; hf < 2; hf++) {
                const int r = row0 + tm * 16 + gr + hf * 8;
                float v0 = acc[tm][tn][hf * 2 + 0] + bb.x;
                float v1 = acc[tm][tn][hf * 2 + 1] + bb.y;
                __nv_bfloat16 h0, l0, h1, l1;
                split2(v0, h0, l0);
                split2(v1, h1, l1);
                const size_t o = (size_t)r * DIM + c;
                *reinterpret_cast<uint32_t*>(&g_qryh[o]) = packbf(h0, h1);
                *reinterpret_cast<uint32_t*>(&g_qryl[o]) = packbf(l0, l1);
            }
    }
}

// ---------------------------------------------------------------------------
// GEMM 2: scores[b][c, q] = SCALE * ch[b,c,:] . query[b,q,:]; mask -> -1e30
// grid (8, 16, 8)
// ---------------------------------------------------------------------------
__global__ __launch_bounds__(256, 1) void k_gemm_scores(const int* __restrict__ qmask) {
    float acc[4][4][4] = {};
    const int z = blockIdx.z;
    const size_t aoff = (size_t)z * LC * DIM + (size_t)blockIdx.y * 128 * DIM;
    const size_t boff = (size_t)z * LQ * DIM + (size_t)blockIdx.x * 128 * DIM;
    mainloop(g_chh + aoff, g_chl + aoff, DIM, g_qryh + boff, g_qryl + boff, DIM, DIM / 64, acc);

    const int lane = threadIdx.x & 31, wid = threadIdx.x >> 5;
    const int wm = wid & 1, wn = wid >> 1;
    const int gr = lane >> 2, gc = (lane & 3) * 2;
    const int row0 = blockIdx.y * 128 + wm * 64, col0 = blockIdx.x * 128 + wn * 32;
    float* sbase = g_scores + (size_t)z * LC * LQ;
    const int* mrow = qmask + (size_t)z * LQ;
    #pragma unroll
    for (int tn = 0; tn < 4; tn++) {
        const int c = col0 + tn * 8 + gc;
        const int2 mk = *reinterpret_cast<const int2*>(mrow + c);
        #pragma unroll
        for (int tm = 0; tm < 4; tm++)
            #pragma unroll
            for (int hf = 0; hf < 2; hf++) {
                const int r = row0 + tm * 16 + gr + hf * 8;
                float2 v;
                v.x = mk.x ? acc[tm][tn][hf * 2 + 0] * SCALE_F : NEG_INF;
                v.y = mk.y ? acc[tm][tn][hf * 2 + 1] * SCALE_F : NEG_INF;
                *reinterpret_cast<float2*>(sbase + (size_t)r * LQ + c) = v;
            }
    }
}

// ---------------------------------------------------------------------------
// GEMM 3: attn[b][c, d] = P[b][c, :] . qhT[b][d, :]  (K=LQ). grid (6, 16, 8)
// writes fp32 into out cols [768, 1536)
// ---------------------------------------------------------------------------
__global__ __launch_bounds__(256, 1) void k_gemm_out(float* __restrict__ out) {
    float acc[4][4][4] = {};
    const int z = blockIdx.z;
    const size_t aoff = (size_t)z * LC * LQ + (size_t)blockIdx.y * 128 * LQ;
    const size_t boff = (size_t)z * DIM * LQ + (size_t)blockIdx.x * 128 * LQ;
    mainloop(g_ph + aoff, g_pl + aoff, LQ, g_qth + boff, g_qtl + boff, LQ, LQ / 64, acc);

    const int lane = threadIdx.x & 31, wid = threadIdx.x >> 5;
    const int wm = wid & 1, wn = wid >> 1;
    const int gr = lane >> 2, gc = (lane & 3) * 2;
    const int row0 = blockIdx.y * 128 + wm * 64, col0 = blockIdx.x * 128 + wn * 32;
    float* obase = out + (size_t)z * LC * ODIM + DIM;
    #pragma unroll
    for (int tn = 0; tn < 4; tn++) {
        const int c = col0 + tn * 8 + gc;
        #pragma unroll
        for (int tm = 0; tm < 4; tm++)
            #pragma unroll
            for (int hf = 0; hf < 2; hf++) {
                const int r = row0 + tm * 16 + gr + hf * 8;
                float2 v = make_float2(acc[tm][tn][hf * 2 + 0], acc[tm][tn][hf * 2 + 1]);
                *reinterpret_cast<float2*>(obase + (size_t)r * ODIM + c) = v;
            }
    }
}

// ---------------------------------------------------------------------------
// fp32 -> bf16 hi/lo split (float4 granularity)
// ---------------------------------------------------------------------------
__global__ __launch_bounds__(256) void k_split(const float* __restrict__ src,
                                               __nv_bfloat16* __restrict__ hi,
                                               __nv_bfloat16* __restrict__ lo, int n4) {
    int i = blockIdx.x * blockDim.x + threadIdx.x;
    if (i >= n4) return;
    float4 x = reinterpret_cast<const float4*>(src)[i];
    __nv_bfloat16 h0, h1, h2, h3, l0, l1, l2, l3;
    split2(x.x, h0, l0); split2(x.y, h1, l1);
    split2(x.z, h2, l2); split2(x.w, h3, l3);
    reinterpret_cast<uint2*>(hi)[i] = make_uint2(packbf(h0, h1), packbf(h2, h3));
    reinterpret_cast<uint2*>(lo)[i] = make_uint2(packbf(l0, l1), packbf(l2, l3));
}

// ---------------------------------------------------------------------------
// qh transpose + split: [b, q, d] fp32 -> [b, d, q] bf16 hi/lo
// grid (24, 32, 8), block (32, 8)
// ---------------------------------------------------------------------------
__global__ __launch_bounds__(256) void k_tsplit(const float* __restrict__ qh) {
    __shared__ float t[32][33];
    int z = blockIdx.z;
    int d0 = blockIdx.x * 32, q0 = blockIdx.y * 32;
    const float* src = qh + (size_t)z * LQ * DIM;
    int tx = threadIdx.x, ty = threadIdx.y;
    #pragma unroll
    for (int i = 0; i < 4; i++)
        t[ty + 8 * i][tx] = src[(size_t)(q0 + ty + 8 * i) * DIM + d0 + tx];
    __syncthreads();
    __nv_bfloat16* dh = g_qth + (size_t)z * DIM * LQ;
    __nv_bfloat16* dl = g_qtl + (size_t)z * DIM * LQ;
    #pragma unroll
    for (int i = 0; i < 4; i++) {
        float v = t[tx][ty + 8 * i];
        __nv_bfloat16 h, l;
        split2(v, h, l);
        size_t o = (size_t)(d0 + ty + 8 * i) * LQ + q0 + tx;
        dh[o] = h;
        dl[o] = l;
    }
}

// ---------------------------------------------------------------------------
// Row softmax over Lq=1024; fp32 in, P as bf16 hi/lo out. grid 16384 x 256
// ---------------------------------------------------------------------------
__global__ __launch_bounds__(256) void k_softmax() {
    const size_t rowoff = (size_t)blockIdx.x * LQ;
    const float* p = g_scores + rowoff;
    const int t = threadIdx.x;
    float4 v = reinterpret_cast<const float4*>(p)[t];

    __shared__ float red[8];
    float m = fmaxf(fmaxf(v.x, v.y), fmaxf(v.z, v.w));
    #pragma unroll
    for (int o = 16; o; o >>= 1) m = fmaxf(m, __shfl_xor_sync(0xffffffffu, m, o));
    if ((t & 31) == 0) red[t >> 5] = m;
    __syncthreads();
    m = red[0];
    #pragma unroll
    for (int w = 1; w < 8; w++) m = fmaxf(m, red[w]);
    __syncthreads();

    v.x = __expf(v.x - m); v.y = __expf(v.y - m);
    v.z = __expf(v.z - m); v.w = __expf(v.w - m);
    float s = v.x + v.y + v.z + v.w;
    #pragma unroll
    for (int o = 16; o; o >>= 1) s += __shfl_xor_sync(0xffffffffu, s, o);
    if ((t & 31) == 0) red[t >> 5] = s;
    __syncthreads();
    s = red[0];
    #pragma unroll
    for (int w = 1; w < 8; w++) s += red[w];

    float inv = 1.0f / s;
    v.x *= inv; v.y *= inv; v.z *= inv; v.w *= inv;

    __nv_bfloat16 h0, h1, h2, h3, l0, l1, l2, l3;
    split2(v.x, h0, l0); split2(v.y, h1, l1);
    split2(v.z, h2, l2); split2(v.w, h3, l3);
    reinterpret_cast<uint2*>(g_ph + rowoff)[t] = make_uint2(packbf(h0, h1), packbf(h2, h3));
    reinterpret_cast<uint2*>(g_pl + rowoff)[t] = make_uint2(packbf(l0, l1), packbf(l2, l3));
}

// ---------------------------------------------------------------------------
// out[b][c][0:768] = context_hiddens (fp32 copy)
// ---------------------------------------------------------------------------
__global__ __launch_bounds__(256) void k_copy(const float* __restrict__ ch,
                                              float* __restrict__ out) {
    const size_t total4 = (size_t)BATCH * LC * (DIM / 4);
    for (size_t idx = (size_t)blockIdx.x * blockDim.x + threadIdx.x; idx < total4;
         idx += (size_t)gridDim.x * blockDim.x) {
        size_t row = idx / (DIM / 4);
        size_t d4 = idx % (DIM / 4);
        reinterpret_cast<float4*>(out)[row * (ODIM / 4) + d4] =
            reinterpret_cast<const float4*>(ch)[idx];
    }
}

// ---------------------------------------------------------------------------
extern "C" void kernel_launch(void* const* d_in, const int* in_sizes, int n_in,
                              void* d_out, int out_size) {
    const float* ch    = (const float*)d_in[0];
    const float* qh    = (const float*)d_in[2];
    const int*   qmask = (const int*)d_in[3];
    const float* W     = (const float*)d_in[4];
    const float* bias  = (const float*)d_in[5];
    float*       out   = (float*)d_out;

    cudaFuncSetAttribute(k_gemm_query, cudaFuncAttributeMaxDynamicSharedMemorySize, SMEM_DYN);
    cudaFuncSetAttribute(k_gemm_scores, cudaFuncAttributeMaxDynamicSharedMemorySize, SMEM_DYN);
    cudaFuncSetAttribute(k_gemm_out, cudaFuncAttributeMaxDynamicSharedMemorySize, SMEM_DYN);

    __nv_bfloat16 *chh, *chl, *qhh, *qhl, *wh, *wl;
    cudaGetSymbolAddress((void**)&chh, g_chh); cudaGetSymbolAddress((void**)&chl, g_chl);
    cudaGetSymbolAddress((void**)&qhh, g_qhh); cudaGetSymbolAddress((void**)&qhl, g_qhl);
    cudaGetSymbolAddress((void**)&wh, g_wh);   cudaGetSymbolAddress((void**)&wl, g_wl);

    int n4_ch = BATCH * LC * DIM / 4;
    int n4_qh = BATCH * LQ * DIM / 4;
    int n4_w  = DIM * DIM / 4;
    k_split<<<(n4_ch + 255) / 256, 256>>>(ch, chh, chl, n4_ch);
    k_split<<<(n4_qh + 255) / 256, 256>>>(qh, qhh, qhl, n4_qh);
    k_split<<<(n4_w + 255) / 256, 256>>>(W, wh, wl, n4_w);
    k_tsplit<<<dim3(DIM / 32, LQ / 32, BATCH), dim3(32, 8)>>>(qh);

    k_gemm_query<<<dim3(DIM / 128, BATCH * LQ / 128), 256, SMEM_DYN>>>(bias);
    k_gemm_scores<<<dim3(LQ / 128, LC / 128, BATCH), 256, SMEM_DYN>>>(qmask);
    k_softmax<<<BATCH * LC, 256>>>();
    k_gemm_out<<<dim3(DIM / 128, LC / 128, BATCH), 256, SMEM_DYN>>>(out);
    k_copy<<<1184, 256>>>(ch, out);
}